// round 9
// baseline (speedup 1.0000x reference)
#include <cuda_runtime.h>
#include <cuda_bf16.h>

#define SDIM    4096
#define HDIM    16
#define PDIM    64
#define NDIM    64
#define LCHUNK  64
#define NCHUNK  64
#define NBH     128
#define THRESH  14.0f     // exp(-14)=8e-7; truncation ~1e-5 rel << 1e-3 budget
#define CAP     4         // chunk slots in smem
#define PRE0    (NCHUNK - CAP)   // 60
#define THREADS 256
#define NHALF   32        // n-columns per block
#define WIN     512       // backward A-scan window (8 chunks)

// Dynamic smem (floats):
//   xs : [CAP][64][64]  full X tiles (scaled in place)   64KB
//   bs : [CAP][64][32]  B half tiles                     32KB
//   ws : [SDIM]         decay weights                    16KB
#define XS_SLOT (LCHUNK * PDIM)    // 4096
#define BS_SLOT (LCHUNK * NHALF)   // 2048
#define XS_OFF  0
#define BS_OFF  (CAP * XS_SLOT)                // 16384
#define WS_OFF  (BS_OFF + CAP * BS_SLOT)       // 24576
#define SMEM_BYTES ((WS_OFF + SDIM) * 4)       // 114688 B = 112KB

__device__ __forceinline__ void ffma2(unsigned long long& d,
                                      unsigned long long a,
                                      unsigned long long b) {
    asm("fma.rn.f32x2 %0, %1, %2, %0;" : "+l"(d) : "l"(a), "l"(b));
}
__device__ __forceinline__ unsigned long long pack2(float lo, float hi) {
    unsigned long long r;
    asm("mov.b64 %0, {%1, %2};" : "=l"(r) : "f"(lo), "f"(hi));
    return r;
}
__device__ __forceinline__ void unpack2(unsigned long long v, float& lo, float& hi) {
    asm("mov.b64 {%0, %1}, %2;" : "=f"(lo), "=f"(hi) : "l"(v));
}
__device__ __forceinline__ void cp16(float* smem_dst, const float4* gmem_src) {
    unsigned sptr = (unsigned)__cvta_generic_to_shared(smem_dst);
    asm volatile("cp.async.cg.shared.global [%0], [%1], 16;"
                 :: "r"(sptr), "l"(gmem_src) : "memory");
}

union F4U2 { float4 f4; unsigned long long u2[2]; };

// Issue cp.async for one chunk into slot: full X + this block's B half.
__device__ __forceinline__ void load_chunk(float* sm, int slot, int chunk,
                                           int b, int h, int nh, int tid,
                                           const float4* X4, const float4* B4) {
    const long tbase = (long)(b * SDIM + chunk * LCHUNK) * HDIM + h;
    float* xsl = sm + XS_OFF + slot * XS_SLOT;
    float* bsl = sm + BS_OFF + slot * BS_SLOT;
    #pragma unroll
    for (int k = 0; k < 4; k++) {            // X: 1024 float4
        const int i   = k * THREADS + tid;
        const int row = i >> 4;
        const int col = i & 15;
        cp16(xsl + row * 64 + col * 4, X4 + (tbase + (long)row * HDIM) * 16 + col);
    }
    #pragma unroll
    for (int k = 0; k < 2; k++) {            // B half: 512 float4
        const int i   = k * THREADS + tid;
        const int row = i >> 3;
        const int col = i & 7;
        cp16(bsl + row * NHALF + col * 4,
             B4 + (tbase + (long)row * HDIM) * 16 + nh * 8 + col);
    }
}

// Scale X rows in place by decay weight (same thread reads+writes).
__device__ __forceinline__ void scale_chunk(float* sm, const float* ws,
                                            int slot, int chunk, int tid) {
    float* xsl = sm + XS_OFF + slot * XS_SLOT;
    #pragma unroll
    for (int k = 0; k < 4; k++) {
        const int i   = k * THREADS + tid;
        const int row = i >> 4;
        const int col = i & 15;
        const float w = ws[chunk * LCHUNK + row];
        float4 v = *(const float4*)&xsl[row * 64 + col * 4];
        v.x *= w; v.y *= w; v.z *= w; v.w *= w;
        *(float4*)&xsl[row * 64 + col * 4] = v;
    }
}

// Rank-64 update: 4p x 2n per thread. 8 instr per l-iter.
__device__ __forceinline__ void compute_chunk(const float* sm, int slot,
                                              int p0, int n0,
                                              unsigned long long acc[2][2]) {
    const float* xsl = sm + XS_OFF + slot * XS_SLOT;
    const float* bsl = sm + BS_OFF + slot * BS_SLOT;
    #pragma unroll 8
    for (int l = 0; l < LCHUNK; l++) {
        F4U2 xa;
        xa.f4 = *(const float4*)&xsl[l * 64 + p0];
        const float2 bv = *(const float2*)&bsl[l * NHALF + n0];
        const unsigned long long b0 = pack2(bv.x, bv.x);
        const unsigned long long b1 = pack2(bv.y, bv.y);
        ffma2(acc[0][0], xa.u2[0], b0);
        ffma2(acc[0][1], xa.u2[0], b1);
        ffma2(acc[1][0], xa.u2[1], b0);
        ffma2(acc[1][1], xa.u2[1], b1);
    }
}

__global__ void __launch_bounds__(THREADS)
fused_mamba_kernel(const float* __restrict__ X,
                   const float* __restrict__ A,
                   const float* __restrict__ B,
                   float* __restrict__ out) {
    extern __shared__ float sm[];
    float* ws = sm + WS_OFF;

    __shared__ float warpsum[8];
    __shared__ int   s_start;

    const int bh   = blockIdx.x;
    const int nh   = blockIdx.y;        // n-half (0/1)
    const int b    = bh >> 4;
    const int h    = bh & 15;
    const int tid  = threadIdx.x;
    const int lane = tid & 31;
    const int warp = tid >> 5;
    const int p0   = (tid & 15) << 2;   // 4 p-values
    const int n0   = (tid >> 4) << 1;   // 2 n-values (within half)

    const float4* X4 = (const float4*)X;
    const float4* B4 = (const float4*)B;
    const float*  Ab = A + (long)b * SDIM * HDIM + h;

    if (tid == 0) s_start = NCHUNK - 1;

    // ---- Speculative prefetch: chunks 60..63 ------------------------------
    #pragma unroll
    for (int s = 0; s < CAP; s++)
        load_chunk(sm, s, PRE0 + s, b, h, nh, tid, X4, B4);
    asm volatile("cp.async.commit_group;" ::: "memory");

    // ---- Backward windowed A-scan (usually ONE window) --------------------
    float suffixBeyond = 0.0f;
    int winEnd = SDIM;
    for (;;) {
        const int winStart = winEnd - WIN;
        const float a0 = Ab[(winStart + 2 * tid)     * HDIM];
        const float a1 = Ab[(winStart + 2 * tid + 1) * HDIM];
        float sc = a0 + a1;
        #pragma unroll
        for (int d = 1; d < 32; d <<= 1) {
            float o = __shfl_up_sync(0xffffffffu, sc, d);
            if (lane >= d) sc += o;
        }
        if (lane == 31) warpsum[warp] = sc;
        __syncthreads();
        if (warp == 0 && lane < 8) {
            float v = warpsum[lane];
            #pragma unroll
            for (int d = 1; d < 8; d <<= 1) {
                float o = __shfl_up_sync(0x000000ffu, v, d);
                if (lane >= d) v += o;
            }
            warpsum[lane] = v;
        }
        __syncthreads();
        const float off   = (warp > 0) ? warpsum[warp - 1] : 0.0f;
        const float total = warpsum[7];
        const float cs1 = sc + off;
        const float cs0 = cs1 - a1;
        float2 wv;
        wv.x = __expf(total - cs0 + suffixBeyond);
        wv.y = __expf(total - cs1 + suffixBeyond);
        ((float2*)(ws + winStart))[tid] = wv;
        if (lane == 31) {                       // t1 = last t of its chunk
            const float Uj = total - cs1 + suffixBeyond;
            if (Uj > -THRESH) atomicMin(&s_start, (winStart + 2 * tid + 1) >> 6);
        }
        const float newSuffix = suffixBeyond + total;
        __syncthreads();
        if (winStart == 0 || newSuffix < -THRESH) break;
        suffixBeyond = newSuffix;
        winEnd = winStart;
    }
    const int start = s_start;
    __syncthreads();

    unsigned long long acc[2][2] = {{0ull, 0ull}, {0ull, 0ull}};

    // ---- Prefetched chunks: scale, then compute ----------------------------
    asm volatile("cp.async.wait_group 0;" ::: "memory");
    __syncthreads();

    const int s0 = (start > PRE0) ? (start - PRE0) : 0;
    for (int s = s0; s < CAP; s++)
        scale_chunk(sm, ws, s, PRE0 + s, tid);
    __syncthreads();

    for (int s = s0; s < CAP; s++)
        compute_chunk(sm, s, p0, n0, acc);

    // ---- Fallback: earlier active chunks (start<60, ~never) ---------------
    for (int c0 = start; c0 < PRE0; c0 += CAP) {
        const int nc = min(CAP, PRE0 - c0);
        __syncthreads();
        for (int c = 0; c < nc; c++)
            load_chunk(sm, c, c0 + c, b, h, nh, tid, X4, B4);
        asm volatile("cp.async.commit_group;" ::: "memory");
        asm volatile("cp.async.wait_group 0;" ::: "memory");
        __syncthreads();
        for (int c = 0; c < nc; c++)
            scale_chunk(sm, ws, c, c0 + c, tid);
        __syncthreads();
        for (int c = 0; c < nc; c++)
            compute_chunk(sm, c, p0, n0, acc);
    }

    // ---- Write out[bh, p, nh*32 + n0 .. +1] --------------------------------
    float* ob = out + (long)bh * PDIM * NDIM + nh * NHALF + n0;
    float p_lo[4], p_hi[4];
    unpack2(acc[0][0], p_lo[0], p_lo[1]);   // n0   : p0, p0+1
    unpack2(acc[1][0], p_lo[2], p_lo[3]);   // n0   : p0+2, p0+3
    unpack2(acc[0][1], p_hi[0], p_hi[1]);   // n0+1 : p0, p0+1
    unpack2(acc[1][1], p_hi[2], p_hi[3]);   // n0+1 : p0+2, p0+3
    #pragma unroll
    for (int i = 0; i < 4; i++) {
        float2 v; v.x = p_lo[i]; v.y = p_hi[i];
        *(float2*)(ob + (p0 + i) * NDIM) = v;
    }
}

// ---------------------------------------------------------------------------
extern "C" void kernel_launch(void* const* d_in, const int* in_sizes, int n_in,
                              void* d_out, int out_size) {
    const float* X = (const float*)d_in[0];
    const float* A = (const float*)d_in[1];
    const float* B = (const float*)d_in[2];
    float* out = (float*)d_out;

    cudaFuncSetAttribute(fused_mamba_kernel,
                         cudaFuncAttributeMaxDynamicSharedMemorySize,
                         SMEM_BYTES);
    dim3 grid(NBH, 2);
    fused_mamba_kernel<<<grid, THREADS, SMEM_BYTES>>>(X, A, B, out);
}

// round 10
// speedup vs baseline: 1.2393x; 1.2393x over previous
#include <cuda_runtime.h>
#include <cuda_bf16.h>

#define SDIM    4096
#define HDIM    16
#define PDIM    64
#define NDIM    64
#define LCHUNK  64
#define NCHUNK  64
#define NBH     128
#define THRESH  14.0f     // exp(-14)=8e-7; truncation ~1e-5 rel << 1e-3 budget
#define CAP     5         // chunk slots in smem (speculative prefetch 59..63)
#define PRE0    (NCHUNK - CAP)   // 59
#define THREADS 256
#define WIN     512       // backward A-scan window (8 chunks)

// Dynamic smem (floats):
//   xs : [CAP][64][64]  X tiles (scaled in place)   80KB
//   bs : [CAP][64][64]  B tiles                     80KB
//   ws : [SDIM]         decay weights               16KB
#define XS_SLOT 4096
#define BS_SLOT 4096
#define XS_OFF  0
#define BS_OFF  (CAP * XS_SLOT)
#define WS_OFF  (BS_OFF + CAP * BS_SLOT)
#define SMEM_BYTES ((WS_OFF + SDIM) * 4)   // 180224 B

__device__ __forceinline__ void ffma2(unsigned long long& d,
                                      unsigned long long a,
                                      unsigned long long b) {
    asm("fma.rn.f32x2 %0, %1, %2, %0;" : "+l"(d) : "l"(a), "l"(b));
}
__device__ __forceinline__ void fadd2(unsigned long long& d, unsigned long long a) {
    asm("add.rn.f32x2 %0, %0, %1;" : "+l"(d) : "l"(a));
}
__device__ __forceinline__ unsigned long long pack2(float lo, float hi) {
    unsigned long long r;
    asm("mov.b64 %0, {%1, %2};" : "=l"(r) : "f"(lo), "f"(hi));
    return r;
}
__device__ __forceinline__ void unpack2(unsigned long long v, float& lo, float& hi) {
    asm("mov.b64 {%0, %1}, %2;" : "=f"(lo), "=f"(hi) : "l"(v));
}
__device__ __forceinline__ void cp16(float* smem_dst, const float4* gmem_src) {
    unsigned sptr = (unsigned)__cvta_generic_to_shared(smem_dst);
    asm volatile("cp.async.cg.shared.global [%0], [%1], 16;"
                 :: "r"(sptr), "l"(gmem_src) : "memory");
}

union F4U2 { float4 f4; unsigned long long u2[2]; };

// Issue cp.async for one chunk into slot.
__device__ __forceinline__ void load_chunk(float* sm, int slot, int chunk,
                                           int b, int h, int tid,
                                           const float4* X4, const float4* B4) {
    const long tbase = (long)(b * SDIM + chunk * LCHUNK) * HDIM + h;
    float* xsl = sm + XS_OFF + slot * XS_SLOT;
    float* bsl = sm + BS_OFF + slot * BS_SLOT;
    #pragma unroll
    for (int k = 0; k < 4; k++) {
        const int i   = k * THREADS + tid;   // 0..1023
        const int row = i >> 4;
        const int col = i & 15;
        const long g  = (tbase + (long)row * HDIM) * 16 + col;
        cp16(xsl + row * 64 + col * 4, X4 + g);
        cp16(bsl + row * 64 + col * 4, B4 + g);
    }
}

// Scale X rows in place by decay weight (same thread reads+writes).
__device__ __forceinline__ void scale_chunk(float* sm, const float* ws,
                                            int slot, int chunk, int tid) {
    float* xsl = sm + XS_OFF + slot * XS_SLOT;
    #pragma unroll
    for (int k = 0; k < 4; k++) {
        const int i   = k * THREADS + tid;
        const int row = i >> 4;
        const int col = i & 15;
        const float w = ws[chunk * LCHUNK + row];
        float4 v = *(const float4*)&xsl[row * 64 + col * 4];
        v.x *= w; v.y *= w; v.z *= w; v.w *= w;
        *(float4*)&xsl[row * 64 + col * 4] = v;
    }
}

// 8p x 8n register tile, this l-group's 16 rows. 32 FFMA2 per iter.
__device__ __forceinline__ void compute_chunk(const float* sm, int slot,
                                              int lg, int p0, int n0,
                                              unsigned long long acc[4][8]) {
    const float* xsl = sm + XS_OFF + slot * XS_SLOT + lg * 16 * 64;
    const float* bsl = sm + BS_OFF + slot * BS_SLOT + lg * 16 * 64;
    #pragma unroll 4
    for (int l = 0; l < 16; l++) {
        F4U2 xa0, xa1;
        xa0.f4 = *(const float4*)&xsl[l * 64 + p0];
        xa1.f4 = *(const float4*)&xsl[l * 64 + p0 + 4];
        const float4 b0 = *(const float4*)&bsl[l * 64 + n0];
        const float4 b1 = *(const float4*)&bsl[l * 64 + n0 + 4];
        unsigned long long bd[8];
        bd[0] = pack2(b0.x, b0.x); bd[1] = pack2(b0.y, b0.y);
        bd[2] = pack2(b0.z, b0.z); bd[3] = pack2(b0.w, b0.w);
        bd[4] = pack2(b1.x, b1.x); bd[5] = pack2(b1.y, b1.y);
        bd[6] = pack2(b1.z, b1.z); bd[7] = pack2(b1.w, b1.w);
        #pragma unroll
        for (int nj = 0; nj < 8; nj++) {
            ffma2(acc[0][nj], xa0.u2[0], bd[nj]);
            ffma2(acc[1][nj], xa0.u2[1], bd[nj]);
            ffma2(acc[2][nj], xa1.u2[0], bd[nj]);
            ffma2(acc[3][nj], xa1.u2[1], bd[nj]);
        }
    }
}

__global__ void __launch_bounds__(THREADS)
fused_mamba_kernel(const float* __restrict__ X,
                   const float* __restrict__ A,
                   const float* __restrict__ B,
                   float* __restrict__ out) {
    extern __shared__ float sm[];
    float* ws = sm + WS_OFF;

    __shared__ float warpsum[8];
    __shared__ int   s_start;

    const int bh   = blockIdx.x;
    const int b    = bh >> 4;
    const int h    = bh & 15;
    const int tid  = threadIdx.x;
    const int lane = tid & 31;
    const int warp = tid >> 5;
    const int lg   = tid >> 6;          // l-group 0..3 (16 l each)
    const int r    = tid & 63;          // slot in 64-thread tile group
    const int p0   = (r >> 3) << 3;     // 8 p-values
    const int n0   = (r & 7) << 3;      // 8 n-values

    const float4* X4 = (const float4*)X;
    const float4* B4 = (const float4*)B;
    const float*  Ab = A + (long)b * SDIM * HDIM + h;

    if (tid == 0) s_start = NCHUNK - 1;

    // ---- Speculative prefetch: chunks 59..63 -------------------------------
    #pragma unroll
    for (int s = 0; s < CAP; s++)
        load_chunk(sm, s, PRE0 + s, b, h, tid, X4, B4);
    asm volatile("cp.async.commit_group;" ::: "memory");

    // ---- Backward windowed A-scan (usually ONE window) ---------------------
    float suffixBeyond = 0.0f;
    int winEnd = SDIM;
    for (;;) {
        const int winStart = winEnd - WIN;
        const float a0 = Ab[(winStart + 2 * tid)     * HDIM];
        const float a1 = Ab[(winStart + 2 * tid + 1) * HDIM];
        float sc = a0 + a1;
        #pragma unroll
        for (int d = 1; d < 32; d <<= 1) {
            float o = __shfl_up_sync(0xffffffffu, sc, d);
            if (lane >= d) sc += o;
        }
        if (lane == 31) warpsum[warp] = sc;
        __syncthreads();
        if (warp == 0 && lane < 8) {
            float v = warpsum[lane];
            #pragma unroll
            for (int d = 1; d < 8; d <<= 1) {
                float o = __shfl_up_sync(0x000000ffu, v, d);
                if (lane >= d) v += o;
            }
            warpsum[lane] = v;
        }
        __syncthreads();
        const float off   = (warp > 0) ? warpsum[warp - 1] : 0.0f;
        const float total = warpsum[7];
        const float cs1 = sc + off;
        const float cs0 = cs1 - a1;
        float2 wv;
        wv.x = __expf(total - cs0 + suffixBeyond);
        wv.y = __expf(total - cs1 + suffixBeyond);
        ((float2*)(ws + winStart))[tid] = wv;
        if (lane == 31) {                       // t1 = last t of its chunk
            const float Uj = total - cs1 + suffixBeyond;
            if (Uj > -THRESH) atomicMin(&s_start, (winStart + 2 * tid + 1) >> 6);
        }
        const float newSuffix = suffixBeyond + total;
        __syncthreads();
        if (winStart == 0 || newSuffix < -THRESH) break;
        suffixBeyond = newSuffix;
        winEnd = winStart;
    }
    const int start = s_start;
    __syncthreads();

    unsigned long long acc[4][8];
    #pragma unroll
    for (int i = 0; i < 4; i++)
        #pragma unroll
        for (int n = 0; n < 8; n++) acc[i][n] = 0ull;

    // ---- Prefetched chunks: scale, then compute -----------------------------
    asm volatile("cp.async.wait_group 0;" ::: "memory");
    __syncthreads();

    const int s0 = (start > PRE0) ? (start - PRE0) : 0;
    for (int s = s0; s < CAP; s++)
        scale_chunk(sm, ws, s, PRE0 + s, tid);
    __syncthreads();

    for (int s = s0; s < CAP; s++)
        compute_chunk(sm, s, lg, p0, n0, acc);

    // ---- Fallback: earlier active chunks (start<59, ~never) ----------------
    for (int c0 = start; c0 < PRE0; c0 += CAP) {
        const int nc = min(CAP, PRE0 - c0);
        __syncthreads();
        for (int c = 0; c < nc; c++)
            load_chunk(sm, c, c0 + c, b, h, tid, X4, B4);
        asm volatile("cp.async.commit_group;" ::: "memory");
        asm volatile("cp.async.wait_group 0;" ::: "memory");
        __syncthreads();
        for (int c = 0; c < nc; c++)
            scale_chunk(sm, ws, c, c0 + c, tid);
        __syncthreads();
        for (int c = 0; c < nc; c++)
            compute_chunk(sm, c, lg, p0, n0, acc);
    }

    // ---- Cross-l-group reduction: groups 1..3 store, group 0 adds ----------
    __syncthreads();
    unsigned long long* buf = (unsigned long long*)sm;   // reuse xs region (48KB)
    if (lg != 0) {
        unsigned long long* dst = buf + (lg - 1) * 2048 + r;
        #pragma unroll
        for (int q = 0; q < 32; q++)
            dst[q * 64] = acc[q >> 3][q & 7];
    }
    __syncthreads();
    if (lg == 0) {
        #pragma unroll
        for (int q = 0; q < 32; q++) {
            #pragma unroll
            for (int g = 0; g < 3; g++)
                fadd2(acc[q >> 3][q & 7], buf[g * 2048 + q * 64 + r]);
        }

        // ---- Write out[bh, p, n]: 8 rows x 8 floats per thread -------------
        float4* out4 = (float4*)out + (long)bh * PDIM * 16;
        #pragma unroll
        for (int pi = 0; pi < 4; pi++) {
            float4 lo0, lo1, hi0, hi1;   // rows p0+2pi (lo) and p0+2pi+1 (hi)
            unpack2(acc[pi][0], lo0.x, hi0.x);
            unpack2(acc[pi][1], lo0.y, hi0.y);
            unpack2(acc[pi][2], lo0.z, hi0.z);
            unpack2(acc[pi][3], lo0.w, hi0.w);
            unpack2(acc[pi][4], lo1.x, hi1.x);
            unpack2(acc[pi][5], lo1.y, hi1.y);
            unpack2(acc[pi][6], lo1.z, hi1.z);
            unpack2(acc[pi][7], lo1.w, hi1.w);
            const int row0 = p0 + 2 * pi;
            out4[row0 * 16 + (n0 >> 2)]           = lo0;
            out4[row0 * 16 + (n0 >> 2) + 1]       = lo1;
            out4[(row0 + 1) * 16 + (n0 >> 2)]     = hi0;
            out4[(row0 + 1) * 16 + (n0 >> 2) + 1] = hi1;
        }
    }
}

// ---------------------------------------------------------------------------
extern "C" void kernel_launch(void* const* d_in, const int* in_sizes, int n_in,
                              void* d_out, int out_size) {
    const float* X = (const float*)d_in[0];
    const float* A = (const float*)d_in[1];
    const float* B = (const float*)d_in[2];
    float* out = (float*)d_out;

    cudaFuncSetAttribute(fused_mamba_kernel,
                         cudaFuncAttributeMaxDynamicSharedMemorySize,
                         SMEM_BYTES);
    fused_mamba_kernel<<<NBH, THREADS, SMEM_BYTES>>>(X, A, B, out);
}

// round 11
// speedup vs baseline: 1.4076x; 1.1359x over previous
#include <cuda_runtime.h>
#include <cuda_bf16.h>

#define SDIM    4096
#define HDIM    16
#define PDIM    64
#define NDIM    64
#define LCHUNK  64
#define NCHUNK  64
#define NBH     128
#define THRESH  10.0f     // exp(-10)=4.5e-5; truncation ~4e-5 rel << 1e-3 budget
#define CAP     3         // chunk slots in smem (speculative prefetch 61..63)
#define PRE0    (NCHUNK - CAP)   // 61
#define THREADS 512
#define WIN     1024      // backward A-scan window (16 chunks)

// Dynamic smem (floats):
//   xs : [CAP][64][64]  X tiles (scaled in place)   48KB
//   bs : [CAP][64][64]  B tiles                     48KB
//   ws : [SDIM]         decay weights               16KB
#define XS_SLOT 4096
#define BS_SLOT 4096
#define XS_OFF  0
#define BS_OFF  (CAP * XS_SLOT)
#define WS_OFF  (BS_OFF + CAP * BS_SLOT)
#define SMEM_BYTES ((WS_OFF + SDIM) * 4)   // 114688 B

__device__ __forceinline__ void ffma2(unsigned long long& d,
                                      unsigned long long a,
                                      unsigned long long b) {
    asm("fma.rn.f32x2 %0, %1, %2, %0;" : "+l"(d) : "l"(a), "l"(b));
}
__device__ __forceinline__ void fadd2(unsigned long long& d, unsigned long long a) {
    asm("add.rn.f32x2 %0, %0, %1;" : "+l"(d) : "l"(a));
}
__device__ __forceinline__ unsigned long long pack2(float lo, float hi) {
    unsigned long long r;
    asm("mov.b64 %0, {%1, %2};" : "=l"(r) : "f"(lo), "f"(hi));
    return r;
}
__device__ __forceinline__ void unpack2(unsigned long long v, float& lo, float& hi) {
    asm("mov.b64 {%0, %1}, %2;" : "=f"(lo), "=f"(hi) : "l"(v));
}
__device__ __forceinline__ void cp16(float* smem_dst, const float4* gmem_src) {
    unsigned sptr = (unsigned)__cvta_generic_to_shared(smem_dst);
    asm volatile("cp.async.cg.shared.global [%0], [%1], 16;"
                 :: "r"(sptr), "l"(gmem_src) : "memory");
}

union F4U2 { float4 f4; unsigned long long u2[2]; };

// Issue cp.async for one chunk into slot.
__device__ __forceinline__ void load_chunk(float* sm, int slot, int chunk,
                                           int b, int h, int tid,
                                           const float4* X4, const float4* B4) {
    const long tbase = (long)(b * SDIM + chunk * LCHUNK) * HDIM + h;
    float* xsl = sm + XS_OFF + slot * XS_SLOT;
    float* bsl = sm + BS_OFF + slot * BS_SLOT;
    #pragma unroll
    for (int k = 0; k < 2; k++) {
        const int i   = k * THREADS + tid;   // 0..1023
        const int row = i >> 4;
        const int col = i & 15;
        const long g  = (tbase + (long)row * HDIM) * 16 + col;
        cp16(xsl + row * 64 + col * 4, X4 + g);
        cp16(bsl + row * 64 + col * 4, B4 + g);
    }
}

// Scale X rows in place by decay weight (same thread reads+writes).
__device__ __forceinline__ void scale_chunk(float* sm, const float* ws,
                                            int slot, int chunk, int tid) {
    float* xsl = sm + XS_OFF + slot * XS_SLOT;
    #pragma unroll
    for (int k = 0; k < 2; k++) {
        const int i   = k * THREADS + tid;
        const int row = i >> 4;
        const int col = i & 15;
        const float w = ws[chunk * LCHUNK + row];
        float4 v = *(const float4*)&xsl[row * 64 + col * 4];
        v.x *= w; v.y *= w; v.z *= w; v.w *= w;
        *(float4*)&xsl[row * 64 + col * 4] = v;
    }
}

// 4p x 4n register tile over this l-group's 32 rows. 8 FFMA2 per iter.
__device__ __forceinline__ void compute_chunk(const float* sm, int slot,
                                              int lh, int p0, int n0,
                                              unsigned long long acc[2][4]) {
    const float* xsl = sm + XS_OFF + slot * XS_SLOT + lh * 32 * 64;
    const float* bsl = sm + BS_OFF + slot * BS_SLOT + lh * 32 * 64;
    #pragma unroll 4
    for (int l = 0; l < 32; l++) {
        F4U2 xa;
        xa.f4 = *(const float4*)&xsl[l * 64 + p0];
        const float4 bv = *(const float4*)&bsl[l * 64 + n0];
        const unsigned long long b0 = pack2(bv.x, bv.x);
        const unsigned long long b1 = pack2(bv.y, bv.y);
        const unsigned long long b2 = pack2(bv.z, bv.z);
        const unsigned long long b3 = pack2(bv.w, bv.w);
        ffma2(acc[0][0], xa.u2[0], b0);
        ffma2(acc[0][1], xa.u2[0], b1);
        ffma2(acc[0][2], xa.u2[0], b2);
        ffma2(acc[0][3], xa.u2[0], b3);
        ffma2(acc[1][0], xa.u2[1], b0);
        ffma2(acc[1][1], xa.u2[1], b1);
        ffma2(acc[1][2], xa.u2[1], b2);
        ffma2(acc[1][3], xa.u2[1], b3);
    }
}

__global__ void __launch_bounds__(THREADS)
fused_mamba_kernel(const float* __restrict__ X,
                   const float* __restrict__ A,
                   const float* __restrict__ B,
                   float* __restrict__ out) {
    extern __shared__ float sm[];
    float* ws = sm + WS_OFF;

    __shared__ float warpsum[16];
    __shared__ int   s_start;

    const int bh   = blockIdx.x;
    const int b    = bh >> 4;
    const int h    = bh & 15;
    const int tid  = threadIdx.x;
    const int lane = tid & 31;
    const int warp = tid >> 5;
    const int lh   = tid >> 8;          // l-half group (0/1)
    const int r    = tid & 255;
    const int p0   = (r >> 4) << 2;     // 4 p-values
    const int n0   = (r & 15) << 2;     // 4 n-values

    const float4* X4 = (const float4*)X;
    const float4* B4 = (const float4*)B;
    const float*  Ab = A + (long)b * SDIM * HDIM + h;

    if (tid == 0) s_start = NCHUNK - 1;

    // ---- Speculative prefetch: chunks 61..63 -------------------------------
    #pragma unroll
    for (int s = 0; s < CAP; s++)
        load_chunk(sm, s, PRE0 + s, b, h, tid, X4, B4);
    asm volatile("cp.async.commit_group;" ::: "memory");

    // ---- Backward windowed A-scan (usually ONE window) ---------------------
    float suffixBeyond = 0.0f;
    int winEnd = SDIM;
    for (;;) {
        const int winStart = winEnd - WIN;
        const float a0 = Ab[(winStart + 2 * tid)     * HDIM];
        const float a1 = Ab[(winStart + 2 * tid + 1) * HDIM];
        float sc = a0 + a1;
        #pragma unroll
        for (int d = 1; d < 32; d <<= 1) {
            float o = __shfl_up_sync(0xffffffffu, sc, d);
            if (lane >= d) sc += o;
        }
        if (lane == 31) warpsum[warp] = sc;
        __syncthreads();
        if (warp == 0 && lane < 16) {
            float v = warpsum[lane];
            #pragma unroll
            for (int d = 1; d < 16; d <<= 1) {
                float o = __shfl_up_sync(0x0000ffffu, v, d);
                if (lane >= d) v += o;
            }
            warpsum[lane] = v;
        }
        __syncthreads();
        const float off   = (warp > 0) ? warpsum[warp - 1] : 0.0f;
        const float total = warpsum[15];
        const float cs1 = sc + off;
        const float cs0 = cs1 - a1;
        float2 wv;
        wv.x = __expf(total - cs0 + suffixBeyond);
        wv.y = __expf(total - cs1 + suffixBeyond);
        ((float2*)(ws + winStart))[tid] = wv;
        if (lane == 31) {                       // t1 ends a chunk
            const float Uj = total - cs1 + suffixBeyond;
            if (Uj > -THRESH) atomicMin(&s_start, (winStart + 2 * tid + 1) >> 6);
        }
        const float newSuffix = suffixBeyond + total;
        __syncthreads();
        if (winStart == 0 || newSuffix < -THRESH) break;
        suffixBeyond = newSuffix;
        winEnd = winStart;
    }
    const int start = s_start;
    __syncthreads();

    unsigned long long acc[2][4];
    #pragma unroll
    for (int i = 0; i < 2; i++)
        #pragma unroll
        for (int n = 0; n < 4; n++) acc[i][n] = 0ull;

    // ---- Prefetched chunks: scale, then compute -----------------------------
    asm volatile("cp.async.wait_group 0;" ::: "memory");
    __syncthreads();

    const int s0 = (start > PRE0) ? (start - PRE0) : 0;
    for (int s = s0; s < CAP; s++)
        scale_chunk(sm, ws, s, PRE0 + s, tid);
    __syncthreads();

    for (int s = s0; s < CAP; s++)
        compute_chunk(sm, s, lh, p0, n0, acc);

    // ---- Fallback: earlier active chunks (start<61, ~never) ----------------
    for (int c0 = start; c0 < PRE0; c0 += CAP) {
        const int nc = min(CAP, PRE0 - c0);
        __syncthreads();
        for (int c = 0; c < nc; c++)
            load_chunk(sm, c, c0 + c, b, h, tid, X4, B4);
        asm volatile("cp.async.commit_group;" ::: "memory");
        asm volatile("cp.async.wait_group 0;" ::: "memory");
        __syncthreads();
        for (int c = 0; c < nc; c++)
            scale_chunk(sm, ws, c, c0 + c, tid);
        __syncthreads();
        for (int c = 0; c < nc; c++)
            compute_chunk(sm, c, lh, p0, n0, acc);
    }

    // ---- Cross-group reduction (group1 -> smem, group0 adds) ---------------
    __syncthreads();
    unsigned long long* buf = (unsigned long long*)sm;   // reuse xs region
    if (lh == 1) {
        #pragma unroll
        for (int q = 0; q < 8; q++)
            buf[q * 256 + r] = acc[q >> 2][q & 3];
    }
    __syncthreads();
    if (lh == 0) {
        #pragma unroll
        for (int q = 0; q < 8; q++)
            fadd2(acc[q >> 2][q & 3], buf[q * 256 + r]);

        // ---- Write out[bh, p, n] --------------------------------------------
        float4* out4 = (float4*)out + (long)bh * PDIM * 16;
        #pragma unroll
        for (int pi = 0; pi < 2; pi++) {
            float4 vlo, vhi;
            unpack2(acc[pi][0], vlo.x, vhi.x);
            unpack2(acc[pi][1], vlo.y, vhi.y);
            unpack2(acc[pi][2], vlo.z, vhi.z);
            unpack2(acc[pi][3], vlo.w, vhi.w);
            out4[(p0 + 2 * pi)     * 16 + (n0 >> 2)] = vlo;
            out4[(p0 + 2 * pi + 1) * 16 + (n0 >> 2)] = vhi;
        }
    }
}

// ---------------------------------------------------------------------------
extern "C" void kernel_launch(void* const* d_in, const int* in_sizes, int n_in,
                              void* d_out, int out_size) {
    const float* X = (const float*)d_in[0];
    const float* A = (const float*)d_in[1];
    const float* B = (const float*)d_in[2];
    float* out = (float*)d_out;

    cudaFuncSetAttribute(fused_mamba_kernel,
                         cudaFuncAttributeMaxDynamicSharedMemorySize,
                         SMEM_BYTES);
    fused_mamba_kernel<<<NBH, THREADS, SMEM_BYTES>>>(X, A, B, out);
}

// round 12
// speedup vs baseline: 1.6617x; 1.1805x over previous
#include <cuda_runtime.h>
#include <cuda_bf16.h>

#define SDIM    4096
#define HDIM    16
#define PDIM    64
#define NDIM    64
#define LCHUNK  64
#define NCHUNK  64
#define NBH     128
#define THRESH  9.0f      // truncation ~6e-5 rel (measured 0.52*exp(-T) scaling)
#define CAP     3         // chunk slots in smem (speculative prefetch 61..63)
#define PRE0    (NCHUNK - CAP)   // 61
#define THREADS 512
#define WIN     1024      // backward A-scan window (16 chunks)

// Dynamic smem (floats):
//   xs : [CAP][64][64]  X tiles (scaled in place)   48KB
//   bs : [CAP][64][64]  B tiles                     48KB
//   ws : [SDIM]         decay weights               16KB
#define XS_SLOT 4096
#define BS_SLOT 4096
#define XS_OFF  0
#define BS_OFF  (CAP * XS_SLOT)
#define WS_OFF  (BS_OFF + CAP * BS_SLOT)
#define SMEM_BYTES ((WS_OFF + SDIM) * 4)   // 114688 B

__device__ __forceinline__ void ffma2(unsigned long long& d,
                                      unsigned long long a,
                                      unsigned long long b) {
    asm("fma.rn.f32x2 %0, %1, %2, %0;" : "+l"(d) : "l"(a), "l"(b));
}
__device__ __forceinline__ void fadd2(unsigned long long& d, unsigned long long a) {
    asm("add.rn.f32x2 %0, %0, %1;" : "+l"(d) : "l"(a));
}
__device__ __forceinline__ unsigned long long pack2(float lo, float hi) {
    unsigned long long r;
    asm("mov.b64 %0, {%1, %2};" : "=l"(r) : "f"(lo), "f"(hi));
    return r;
}
__device__ __forceinline__ void unpack2(unsigned long long v, float& lo, float& hi) {
    asm("mov.b64 {%0, %1}, %2;" : "=f"(lo), "=f"(hi) : "l"(v));
}
__device__ __forceinline__ void cp16(float* smem_dst, const float4* gmem_src) {
    unsigned sptr = (unsigned)__cvta_generic_to_shared(smem_dst);
    asm volatile("cp.async.cg.shared.global [%0], [%1], 16;"
                 :: "r"(sptr), "l"(gmem_src) : "memory");
}

union F4U2 { float4 f4; unsigned long long u2[2]; };

// Issue cp.async for one chunk into slot.
__device__ __forceinline__ void load_chunk(float* sm, int slot, int chunk,
                                           int b, int h, int tid,
                                           const float4* X4, const float4* B4) {
    const long tbase = (long)(b * SDIM + chunk * LCHUNK) * HDIM + h;
    float* xsl = sm + XS_OFF + slot * XS_SLOT;
    float* bsl = sm + BS_OFF + slot * BS_SLOT;
    #pragma unroll
    for (int k = 0; k < 2; k++) {
        const int i   = k * THREADS + tid;   // 0..1023
        const int row = i >> 4;
        const int col = i & 15;
        const long g  = (tbase + (long)row * HDIM) * 16 + col;
        cp16(xsl + row * 64 + col * 4, X4 + g);
        cp16(bsl + row * 64 + col * 4, B4 + g);
    }
}

// Scale X rows in place by decay weight (same thread reads+writes).
__device__ __forceinline__ void scale_chunk(float* sm, const float* ws,
                                            int slot, int chunk, int tid) {
    float* xsl = sm + XS_OFF + slot * XS_SLOT;
    #pragma unroll
    for (int k = 0; k < 2; k++) {
        const int i   = k * THREADS + tid;
        const int row = i >> 4;
        const int col = i & 15;
        const float w = ws[chunk * LCHUNK + row];
        float4 v = *(const float4*)&xsl[row * 64 + col * 4];
        v.x *= w; v.y *= w; v.z *= w; v.w *= w;
        *(float4*)&xsl[row * 64 + col * 4] = v;
    }
}

// 4p x 4n register tile over this l-group's 32 rows, software-pipelined:
// next iteration's LDS issued before this iteration's FFMA block.
__device__ __forceinline__ void compute_chunk(const float* sm, int slot,
                                              int lh, int p0, int n0,
                                              unsigned long long acc[2][4]) {
    const float* xsl = sm + XS_OFF + slot * XS_SLOT + lh * 32 * 64 + p0;
    const float* bsl = sm + BS_OFF + slot * BS_SLOT + lh * 32 * 64 + n0;
    F4U2 xa;   float4 bv;
    xa.f4 = *(const float4*)xsl;
    bv    = *(const float4*)bsl;
    #pragma unroll 8
    for (int l = 0; l < 32; l++) {
        const unsigned long long b0 = pack2(bv.x, bv.x);
        const unsigned long long b1 = pack2(bv.y, bv.y);
        const unsigned long long b2 = pack2(bv.z, bv.z);
        const unsigned long long b3 = pack2(bv.w, bv.w);
        const F4U2 xc = xa;
        if (l < 31) {                         // prefetch next iteration
            xa.f4 = *(const float4*)(xsl + (l + 1) * 64);
            bv    = *(const float4*)(bsl + (l + 1) * 64);
        }
        ffma2(acc[0][0], xc.u2[0], b0);
        ffma2(acc[0][1], xc.u2[0], b1);
        ffma2(acc[0][2], xc.u2[0], b2);
        ffma2(acc[0][3], xc.u2[0], b3);
        ffma2(acc[1][0], xc.u2[1], b0);
        ffma2(acc[1][1], xc.u2[1], b1);
        ffma2(acc[1][2], xc.u2[1], b2);
        ffma2(acc[1][3], xc.u2[1], b3);
    }
}

__global__ void __launch_bounds__(THREADS, 1)
fused_mamba_kernel(const float* __restrict__ X,
                   const float* __restrict__ A,
                   const float* __restrict__ B,
                   float* __restrict__ out) {
    extern __shared__ float sm[];
    float* ws = sm + WS_OFF;

    __shared__ float warpsum[16];
    __shared__ int   s_start;

    const int bh   = blockIdx.x;
    const int b    = bh >> 4;
    const int h    = bh & 15;
    const int tid  = threadIdx.x;
    const int lane = tid & 31;
    const int warp = tid >> 5;
    const int lh   = tid >> 8;          // l-half group (0/1)
    const int r    = tid & 255;
    const int p0   = (r >> 4) << 2;     // 4 p-values
    const int n0   = (r & 15) << 2;     // 4 n-values

    const float4* X4 = (const float4*)X;
    const float4* B4 = (const float4*)B;
    const float*  Ab = A + (long)b * SDIM * HDIM + h;

    if (tid == 0) s_start = NCHUNK - 1;

    // ---- Start the A loads FIRST (uncoalesced, long latency) --------------
    int winEnd = SDIM;
    float a0 = Ab[(winEnd - WIN + 2 * tid)     * HDIM];
    float a1 = Ab[(winEnd - WIN + 2 * tid + 1) * HDIM];

    // ---- Speculative prefetch: chunks 61..63 (overlaps A latency) ---------
    #pragma unroll
    for (int s = 0; s < CAP; s++)
        load_chunk(sm, s, PRE0 + s, b, h, tid, X4, B4);
    asm volatile("cp.async.commit_group;" ::: "memory");

    // ---- Backward windowed A-scan (usually ONE window) ---------------------
    float suffixBeyond = 0.0f;
    for (;;) {
        const int winStart = winEnd - WIN;
        float sc = a0 + a1;
        #pragma unroll
        for (int d = 1; d < 32; d <<= 1) {
            float o = __shfl_up_sync(0xffffffffu, sc, d);
            if (lane >= d) sc += o;
        }
        if (lane == 31) warpsum[warp] = sc;
        __syncthreads();
        if (warp == 0 && lane < 16) {
            float v = warpsum[lane];
            #pragma unroll
            for (int d = 1; d < 16; d <<= 1) {
                float o = __shfl_up_sync(0x0000ffffu, v, d);
                if (lane >= d) v += o;
            }
            warpsum[lane] = v;
        }
        __syncthreads();
        const float off   = (warp > 0) ? warpsum[warp - 1] : 0.0f;
        const float total = warpsum[15];
        const float cs1 = sc + off;
        const float cs0 = cs1 - a1;
        float2 wv;
        wv.x = __expf(total - cs0 + suffixBeyond);
        wv.y = __expf(total - cs1 + suffixBeyond);
        ((float2*)(ws + winStart))[tid] = wv;
        if (lane == 31) {                       // t1 ends a chunk
            const float Uj = total - cs1 + suffixBeyond;
            if (Uj > -THRESH) atomicMin(&s_start, (winStart + 2 * tid + 1) >> 6);
        }
        const float newSuffix = suffixBeyond + total;
        __syncthreads();
        if (winStart == 0 || newSuffix < -THRESH) break;
        suffixBeyond = newSuffix;
        winEnd = winStart;
        a0 = Ab[(winEnd - WIN + 2 * tid)     * HDIM];
        a1 = Ab[(winEnd - WIN + 2 * tid + 1) * HDIM];
    }
    const int start = s_start;
    __syncthreads();

    unsigned long long acc[2][4];
    #pragma unroll
    for (int i = 0; i < 2; i++)
        #pragma unroll
        for (int n = 0; n < 4; n++) acc[i][n] = 0ull;

    // ---- Prefetched chunks: scale, then compute -----------------------------
    asm volatile("cp.async.wait_group 0;" ::: "memory");
    __syncthreads();

    const int s0 = (start > PRE0) ? (start - PRE0) : 0;
    for (int s = s0; s < CAP; s++)
        scale_chunk(sm, ws, s, PRE0 + s, tid);
    __syncthreads();

    for (int s = s0; s < CAP; s++)
        compute_chunk(sm, s, lh, p0, n0, acc);

    // ---- Fallback: earlier active chunks (start<61, ~never) ----------------
    for (int c0 = start; c0 < PRE0; c0 += CAP) {
        const int nc = min(CAP, PRE0 - c0);
        __syncthreads();
        for (int c = 0; c < nc; c++)
            load_chunk(sm, c, c0 + c, b, h, tid, X4, B4);
        asm volatile("cp.async.commit_group;" ::: "memory");
        asm volatile("cp.async.wait_group 0;" ::: "memory");
        __syncthreads();
        for (int c = 0; c < nc; c++)
            scale_chunk(sm, ws, c, c0 + c, tid);
        __syncthreads();
        for (int c = 0; c < nc; c++)
            compute_chunk(sm, c, lh, p0, n0, acc);
    }

    // ---- Cross-group reduction (group1 -> smem, group0 adds) ---------------
    __syncthreads();
    unsigned long long* buf = (unsigned long long*)sm;   // reuse xs region
    if (lh == 1) {
        #pragma unroll
        for (int q = 0; q < 8; q++)
            buf[q * 256 + r] = acc[q >> 2][q & 3];
    }
    __syncthreads();
    if (lh == 0) {
        #pragma unroll
        for (int q = 0; q < 8; q++)
            fadd2(acc[q >> 2][q & 3], buf[q * 256 + r]);

        // ---- Write out[bh, p, n] --------------------------------------------
        float4* out4 = (float4*)out + (long)bh * PDIM * 16;
        #pragma unroll
        for (int pi = 0; pi < 2; pi++) {
            float4 vlo, vhi;
            unpack2(acc[pi][0], vlo.x, vhi.x);
            unpack2(acc[pi][1], vlo.y, vhi.y);
            unpack2(acc[pi][2], vlo.z, vhi.z);
            unpack2(acc[pi][3], vlo.w, vhi.w);
            out4[(p0 + 2 * pi)     * 16 + (n0 >> 2)] = vlo;
            out4[(p0 + 2 * pi + 1) * 16 + (n0 >> 2)] = vhi;
        }
    }
}

// ---------------------------------------------------------------------------
extern "C" void kernel_launch(void* const* d_in, const int* in_sizes, int n_in,
                              void* d_out, int out_size) {
    const float* X = (const float*)d_in[0];
    const float* A = (const float*)d_in[1];
    const float* B = (const float*)d_in[2];
    float* out = (float*)d_out;

    cudaFuncSetAttribute(fused_mamba_kernel,
                         cudaFuncAttributeMaxDynamicSharedMemorySize,
                         SMEM_BYTES);
    fused_mamba_kernel<<<NBH, THREADS, SMEM_BYTES>>>(X, A, B, out);
}